// round 16
// baseline (speedup 1.0000x reference)
#include <cuda_runtime.h>
#include <cuda_bf16.h>
#include <cstdint>

#define T_STEPS 1000
#define BATCH   256
#define NIN     128
#define NHID    512
#define NOUT    128

#define NBLK 64
#define NTHR 384
#define BT 16      // batch rows per b-tile
#define HT 64      // hidden cols per CTA

// smem: 4 s-buffers (A0,A1,B0,B1), each hi(16640)+lo(16640) = 33280 B
#define SLO_OFF 16640
#define SBUF_A  0
#define SBUF_B  66560
#define XT_B    133120   // [btile(2)][parity(2)] x 4352 B = 17408
#define WIN_B   150528   // W_in fragments: 16384
#define OLO_B   166912   // readout-lo exchange, 2 x [16][18] f32 = 2304
#define ST_B    169216   // neuron state: 2 btiles x 256 thr x 64 B = 32768
#define SMEM_BYTES 201984

// bf16 hi/lo s rings (2 slots), b-major, u32 = 2 bf16
__device__ unsigned g_rh[2][BATCH][NHID/2];
__device__ unsigned g_rl[2][BATCH][NHID/2];
// flag barrier state: flags[btile][htile] (128B line per btile)
__device__ unsigned g_flag[16][32];
// closing atomic barrier (generation style; replay-monotonic)
__device__ unsigned g_bcnt[8*32];
__device__ unsigned g_bgen[8*32];

typedef unsigned long long u64;

__device__ __forceinline__ uint32_t smem_u32(const void* p) {
  uint32_t a;
  asm("{ .reg .u64 t; cvta.to.shared.u64 t, %1; cvt.u32.u64 %0, t; }"
      : "=r"(a) : "l"(p));
  return a;
}
__device__ __forceinline__ uint32_t pk2(float lo, float hi) {
  unsigned short a = __bfloat16_as_ushort(__float2bfloat16_rn(lo));
  unsigned short b = __bfloat16_as_ushort(__float2bfloat16_rn(hi));
  return (uint32_t)a | ((uint32_t)b << 16);
}
#define LDSM4(r0,r1,r2,r3,addr) \
  asm volatile("ldmatrix.sync.aligned.m8n8.x4.shared.b16 {%0,%1,%2,%3}, [%4];" \
    : "=r"(r0),"=r"(r1),"=r"(r2),"=r"(r3) : "r"(addr))
#define MMA16816(d, a0,a1,a2,a3, b0,b1) \
  asm volatile("mma.sync.aligned.m16n8k16.row.col.f32.bf16.bf16.f32 " \
    "{%0,%1,%2,%3}, {%4,%5,%6,%7}, {%8,%9}, {%0,%1,%2,%3};" \
    : "+f"((d)[0]),"+f"((d)[1]),"+f"((d)[2]),"+f"((d)[3]) \
    : "r"(a0),"r"(a1),"r"(a2),"r"(a3), "r"(b0),"r"(b1))

// acquire-correct flag poll: volatile L2 loads; fence before returning
__device__ __forceinline__ void poll_flags(const unsigned* fbase, unsigned want) {
  for (;;) {
    unsigned f0, f1, f2, f3, f4, f5, f6, f7;
    asm volatile("ld.global.cg.v4.u32 {%0,%1,%2,%3}, [%4];"
                 : "=r"(f0), "=r"(f1), "=r"(f2), "=r"(f3) : "l"(fbase));
    asm volatile("ld.global.cg.v4.u32 {%0,%1,%2,%3}, [%4];"
                 : "=r"(f4), "=r"(f5), "=r"(f6), "=r"(f7) : "l"(fbase + 4));
    if (f0 >= want && f1 >= want && f2 >= want && f3 >= want &&
        f4 >= want && f5 >= want && f6 >= want && f7 >= want) break;
  }
  asm volatile("fence.acq_rel.gpu;" ::: "memory");   // acquire
}

// One btile phase: GEMM + update + publish + flag (update warps),
// readout hi/lo + out store (readout warps).
#define DO_PHASE(SBASE, AXADDR, OLOP, B0P, STOFF, BTI)                          \
  {                                                                             \
    const uint32_t aH = (SBASE) + aOff;                                         \
    const uint32_t aL = aH + SLO_OFF;                                           \
    if (w < 8) {                                                                \
      if (t < T_STEPS) {                                                        \
        float dA[4]={0,0,0,0}, dB[4]={0,0,0,0};                                 \
        float dC[4]={0,0,0,0}, dD[4]={0,0,0,0}, dX[4]={0,0,0,0};                \
        _Pragma("unroll")                                                       \
        for (int ks = 0; ks < 32; ks += 4) {                                    \
          uint32_t f0,f1,f2,f3; LDSM4(f0,f1,f2,f3, aH + (uint32_t)ks*32);       \
          MMA16816(dA, f0,f1,f2,f3, bf0[ks], bf1[ks]);                          \
          uint32_t g0,g1,g2,g3; LDSM4(g0,g1,g2,g3, aH + (uint32_t)(ks+1)*32);   \
          MMA16816(dB, g0,g1,g2,g3, bf0[ks+1], bf1[ks+1]);                      \
          uint32_t p0,p1,p2,p3; LDSM4(p0,p1,p2,p3, aH + (uint32_t)(ks+2)*32);   \
          MMA16816(dC, p0,p1,p2,p3, bf0[ks+2], bf1[ks+2]);                      \
          uint32_t q0,q1,q2,q3; LDSM4(q0,q1,q2,q3, aH + (uint32_t)(ks+3)*32);   \
          MMA16816(dD, q0,q1,q2,q3, bf0[ks+3], bf1[ks+3]);                      \
        }                                                                       \
        _Pragma("unroll")                                                       \
        for (int ks = 0; ks < 8; ++ks) {                                        \
          uint2 wf = *(const uint2*)(winp + ks*256);                            \
          uint32_t f0,f1,f2,f3; LDSM4(f0,f1,f2,f3, (AXADDR) + (uint32_t)ks*32); \
          MMA16816(dX, f0,f1,f2,f3, wf.x, wf.y);                                \
        }                                                                       \
        float4* stp = (float4*)(smc + (STOFF));                                 \
        float4 v4 = stp[0], a04 = stp[1], a14 = stp[2], sp4 = stp[3];           \
        float vv_[4]={v4.x,v4.y,v4.z,v4.w}, a0_[4]={a04.x,a04.y,a04.z,a04.w};   \
        float a1_[4]={a14.x,a14.y,a14.z,a14.w};                                 \
        float sp_[4]={sp4.x,sp4.y,sp4.z,sp4.w};                                 \
        float bv[4] = {bin.x, bin.y, bin.x, bin.y};                             \
        _Pragma("unroll")                                                       \
        for (int j = 0; j < 4; ++j) {                                           \
          float y = 0.5f*(dA[j]+dB[j]+dC[j]+dD[j]+dX[j]+bv[j]);                 \
          a0_[j] = fmaf(a0_[j],  0.85f, -0.05f*sp_[j]);                         \
          a1_[j] = fmaf(a1_[j], -0.5f,  -0.05f*sp_[j]);                         \
          float it = y + a0_[j] + a1_[j] + 700.0f;                              \
          vv_[j] = vv_[j]*0.99f*(1.0f - 0.05f*sp_[j]) + 0.00101953125f*it;      \
          sp_[j] = 20.0f / (1.0f + __expf(-vv_[j]*0.02f));                      \
        }                                                                       \
        stp[0] = make_float4(vv_[0],vv_[1],vv_[2],vv_[3]);                      \
        stp[1] = make_float4(a0_[0],a0_[1],a0_[2],a0_[3]);                      \
        stp[2] = make_float4(a1_[0],a1_[1],a1_[2],a1_[3]);                      \
        stp[3] = make_float4(sp_[0],sp_[1],sp_[2],sp_[3]);                      \
        const int slot_ = t & 1;                                                \
        float h0f = __bfloat162float(__float2bfloat16_rn(sp_[0]));              \
        float h1f = __bfloat162float(__float2bfloat16_rn(sp_[1]));              \
        float h2f = __bfloat162float(__float2bfloat16_rn(sp_[2]));              \
        float h3f = __bfloat162float(__float2bfloat16_rn(sp_[3]));              \
        __stcg(&g_rh[slot_][(B0P) + r][hh >> 1],     pk2(sp_[0], sp_[1]));      \
        __stcg(&g_rh[slot_][(B0P) + r + 8][hh >> 1], pk2(sp_[2], sp_[3]));      \
        __stcg(&g_rl[slot_][(B0P) + r][hh >> 1],     pk2(sp_[0]-h0f, sp_[1]-h1f)); \
        __stcg(&g_rl[slot_][(B0P) + r + 8][hh >> 1], pk2(sp_[2]-h2f, sp_[3]-h3f)); \
        asm volatile("bar.sync 1, 256;" ::: "memory");                          \
        if (tid == 0) {                                                         \
          asm volatile("fence.acq_rel.gpu;" ::: "memory");                      \
          __stcg(&g_flag[BTI][htile], (unsigned)(t + 1));                       \
        }                                                                       \
      }                                                                         \
    } else if (w < 10) {                                                        \
      float dh0[4]={0,0,0,0}, dh1[4]={0,0,0,0};                                 \
      float dl0[4]={0,0,0,0}, dl1[4]={0,0,0,0};                                 \
      _Pragma("unroll")                                                         \
      for (int ks = 0; ks < 32; ks += 2) {                                      \
        uint32_t f0,f1,f2,f3; LDSM4(f0,f1,f2,f3, aH + (uint32_t)ks*32);         \
        MMA16816(dh0, f0,f1,f2,f3, bf0[ks], bf1[ks]);                           \
        uint32_t g0,g1,g2,g3; LDSM4(g0,g1,g2,g3, aH + (uint32_t)(ks+1)*32);     \
        MMA16816(dh1, g0,g1,g2,g3, bf0[ks+1], bf1[ks+1]);                       \
        uint32_t p0,p1,p2,p3; LDSM4(p0,p1,p2,p3, aL + (uint32_t)ks*32);         \
        MMA16816(dl0, p0,p1,p2,p3, bf0[ks], bf1[ks]);                           \
        uint32_t q0,q1,q2,q3; LDSM4(q0,q1,q2,q3, aL + (uint32_t)(ks+1)*32);     \
        MMA16816(dl1, q0,q1,q2,q3, bf0[ks+1], bf1[ks+1]);                       \
      }                                                                         \
      float d0 = dh0[0]+dh1[0]+dl0[0]+dl1[0];                                   \
      float d1 = dh0[1]+dh1[1]+dl0[1]+dl1[1];                                   \
      float d2 = dh0[2]+dh1[2]+dl0[2]+dl1[2];                                   \
      float d3 = dh0[3]+dh1[3]+dl0[3]+dl1[3];                                   \
      asm volatile("bar.sync 8, 128;" ::: "memory");                            \
      if (t >= 1) {                                                             \
        float* op = out + (size_t)(t-1)*BATCH*NOUT                              \
                  + (size_t)((B0P) + r)*NOUT + o0 + oc;                         \
        *(float2*)op = make_float2(d0 + (OLOP)[r*18 + oc] + bo2.x,              \
                                   d1 + (OLOP)[r*18 + oc + 1] + bo2.y);         \
        float* op2 = op + 8*NOUT;                                               \
        *(float2*)op2 = make_float2(d2 + (OLOP)[(r+8)*18 + oc] + bo2.x,         \
                                    d3 + (OLOP)[(r+8)*18 + oc + 1] + bo2.y);    \
      }                                                                         \
    } else {                                                                    \
      float dA[4]={0,0,0,0}, dB[4]={0,0,0,0};                                   \
      float dC[4]={0,0,0,0}, dD[4]={0,0,0,0};                                   \
      _Pragma("unroll")                                                         \
      for (int ks = 0; ks < 32; ks += 4) {                                      \
        uint32_t f0,f1,f2,f3; LDSM4(f0,f1,f2,f3, aH + (uint32_t)ks*32);         \
        MMA16816(dA, f0,f1,f2,f3, bf0[ks], bf1[ks]);                            \
        uint32_t g0,g1,g2,g3; LDSM4(g0,g1,g2,g3, aH + (uint32_t)(ks+1)*32);     \
        MMA16816(dB, g0,g1,g2,g3, bf0[ks+1], bf1[ks+1]);                        \
        uint32_t p0,p1,p2,p3; LDSM4(p0,p1,p2,p3, aH + (uint32_t)(ks+2)*32);     \
        MMA16816(dC, p0,p1,p2,p3, bf0[ks+2], bf1[ks+2]);                        \
        uint32_t q0,q1,q2,q3; LDSM4(q0,q1,q2,q3, aH + (uint32_t)(ks+3)*32);     \
        MMA16816(dD, q0,q1,q2,q3, bf0[ks+3], bf1[ks+3]);                        \
      }                                                                         \
      int c = (w - 10)*8 + (lane & 3)*2;                                        \
      (OLOP)[r*18 + c]           = dA[0]+dB[0]+dC[0]+dD[0];                     \
      (OLOP)[r*18 + c + 1]       = dA[1]+dB[1]+dC[1]+dD[1];                     \
      (OLOP)[(r+8)*18 + c]       = dA[2]+dB[2]+dC[2]+dD[2];                     \
      (OLOP)[(r+8)*18 + c + 1]   = dA[3]+dB[3]+dC[3]+dD[3];                     \
      asm volatile("bar.sync 8, 128;" ::: "memory");                            \
    }                                                                           \
  }

__global__ void __launch_bounds__(NTHR, 1)
bnn_kernel(const float* __restrict__ x,     // [T, B, NIN]
           const float* __restrict__ W_in,  // [NHID, NIN]
           const float* __restrict__ b_in,  // [NHID]
           const float* __restrict__ W_rec, // [NHID, NHID]
           const float* __restrict__ W_out, // [NOUT, NHID]
           const float* __restrict__ b_out, // [NOUT]
           float* __restrict__ out)         // [T, B, NOUT]
{
  extern __shared__ char smc[];
  const uint32_t smb = smem_u32(smc);
  float* oloA = (float*)(smc + OLO_B);
  float* oloB = oloA + 16*18;

  const int tid = threadIdx.x;
  const int blk = blockIdx.x;
  const int grp = blk >> 3;             // 8 groups (btile pairs)
  const int htile = blk & 7;
  const int bA = grp*2, bB = bA + 1;
  const int b0A = bA * BT, b0B = bB * BT;
  const int h0 = htile * HT;
  const int o0 = htile * 16;
  const int w  = tid >> 5;              // 0..11
  const int lane = tid & 31;

  // ---- B fragments (W_rec / W_out hi / W_out lo) in registers ----
  uint32_t bf0[32], bf1[32];
  {
    const int nn = w*8 + (lane >> 2);
    const float* wr;
    bool is_lo = false;
    if (nn < 64) wr = W_rec + (size_t)(h0 + nn)*NHID;
    else if (nn < 80) wr = W_out + (size_t)(o0 + nn - 64)*NHID;
    else { wr = W_out + (size_t)(o0 + nn - 80)*NHID; is_lo = true; }
    #pragma unroll
    for (int ks = 0; ks < 32; ++ks) {
      int k0 = ks*16 + (lane & 3)*2;
      float w00 = __ldg(wr + k0),     w01 = __ldg(wr + k0 + 1);
      float w10 = __ldg(wr + k0 + 8), w11 = __ldg(wr + k0 + 9);
      if (is_lo) {
        w00 -= __bfloat162float(__float2bfloat16_rn(w00));
        w01 -= __bfloat162float(__float2bfloat16_rn(w01));
        w10 -= __bfloat162float(__float2bfloat16_rn(w10));
        w11 -= __bfloat162float(__float2bfloat16_rn(w11));
      }
      bf0[ks] = pk2(w00, w01);
      bf1[ks] = pk2(w10, w11);
    }
  }

  // ---- W_in B-fragments into smem ----
  if (w < 8) {
    const float* wr = W_in + (size_t)(h0 + w*8 + (lane >> 2))*NIN;
    #pragma unroll
    for (int ks = 0; ks < 8; ++ks) {
      int k0 = ks*16 + (lane & 3)*2;
      uint32_t lo = pk2(__ldg(wr + k0),     __ldg(wr + k0 + 1));
      uint32_t hi = pk2(__ldg(wr + k0 + 8), __ldg(wr + k0 + 9));
      *(uint2*)(smc + WIN_B + (size_t)((w*8 + ks)*32 + lane)*8) = make_uint2(lo, hi);
    }
  }

  // ---- zero s buffers A0/B0 and neuron state; stage x[0] both btiles ----
  for (int i = tid; i < 8320; i += NTHR) {
    ((uint32_t*)(smc + SBUF_A))[i] = 0u;
    ((uint32_t*)(smc + SBUF_B))[i] = 0u;
  }
  for (int i = tid; i < 8192; i += NTHR) ((uint32_t*)(smc + ST_B))[i] = 0u;
  {
    #pragma unroll
    for (int sel = 0; sel < 2; ++sel) {
      int b0P = sel ? b0B : b0A;
      const float4* xr = (const float4*)x + (size_t)b0P*32;
      char* dst = smc + XT_B + sel*8704;
      for (int i = tid; i < 512; i += NTHR) {
        int row = i >> 5, c4 = i & 31;
        float4 vv = __ldcg(xr + row*32 + c4);
        *(uint2*)(dst + row*272 + c4*8) = make_uint2(pk2(vv.x, vv.y), pk2(vv.z, vv.w));
      }
    }
  }
  __syncthreads();

  const uint32_t aOff = (uint32_t)(lane & 15)*1040 + (uint32_t)((lane >> 4) & 1)*16;
  const uint32_t xOff = (uint32_t)(lane & 15)*272 + (uint32_t)((lane >> 4) & 1)*16;
  const char* winp = smc + WIN_B + (size_t)(w*8*32 + lane)*8;

  const int r  = lane >> 2;
  const int hh = h0 + w*8 + (lane & 3)*2;
  float2 bin = make_float2(0.f, 0.f);
  if (w < 8) bin = *(const float2*)(b_in + hh);

  const int oc = ((w - 8) & 1)*8 + (lane & 3)*2;
  float2 bo2 = make_float2(0.f, 0.f);
  if (w >= 8 && w < 10) bo2 = make_float2(__ldg(b_out + o0 + oc),
                                          __ldg(b_out + o0 + oc + 1));

  // per-thread neuron-state smem offsets (update warps: tid 0..255)
  const int stA = ST_B + tid*64;
  const int stB = ST_B + 16384 + tid*64;

  for (int t = 0; t <= T_STEPS; ++t) {
    const uint32_t parity = (uint32_t)(t & 1);
    const uint32_t sbA = smb + SBUF_A + parity*33280;
    const uint32_t sbB = smb + SBUF_B + parity*33280;
    const uint32_t axA = smb + XT_B + parity*4352 + xOff;
    const uint32_t axB = axA + 8704;

    DO_PHASE(sbA, axA, oloA, b0A, stA, bA);
    DO_PHASE(sbB, axB, oloB, b0B, stB, bB);

    if (t == T_STEPS) break;

    // ---- readout warps stage x[t+1] for both btiles ----
    if (w >= 8) {
      int tn = (t + 1 < T_STEPS) ? t + 1 : (T_STEPS - 1);
      #pragma unroll
      for (int sel = 0; sel < 2; ++sel) {
        int b0P = sel ? b0B : b0A;
        const float4* xr = (const float4*)(x + (size_t)tn*BATCH*NIN) + (size_t)b0P*32;
        char* dst = smc + XT_B + sel*8704 + (((t + 1) & 1))*4352;
        int i = (w - 8)*128 + lane;
        #pragma unroll
        for (int jj = 0; jj < 4; ++jj, i += 128) {
          int row = i >> 5, c4 = i & 31;
          float4 vv = __ldcg(xr + row*32 + c4);
          *(uint2*)(dst + row*272 + c4*8) = make_uint2(pk2(vv.x, vv.y), pk2(vv.z, vv.w));
        }
      }
    }

    // ---- poll + restage A, then B (A's wait hidden under phase B compute) ----
    {
      const int slot = t & 1;
      const uint32_t np = (uint32_t)((t + 1) & 1);
      #pragma unroll
      for (int sel = 0; sel < 2; ++sel) {
        poll_flags(&g_flag[sel ? bB : bA][0], (unsigned)(t + 1));
        int b0P = sel ? b0B : b0A;
        char* db = smc + (sel ? SBUF_B : SBUF_A) + np*33280;
        #pragma unroll
        for (int j = 0; j < 6; ++j) {
          int i = j*NTHR + tid;           // 0..2303, valid < 2048
          if (i < 2048) {
            int half = i >> 10;
            int ii = i & 1023;
            int b = ii >> 6, h8 = ii & 63;
            const unsigned* src = half ? &g_rl[slot][b0P + b][h8*4]
                                       : &g_rh[slot][b0P + b][h8*4];
            uint4 vv = __ldcg((const uint4*)src);
            *(uint4*)(db + half*SLO_OFF + b*1040 + h8*16) = vv;
          }
        }
      }
    }
    __syncthreads();
  }

  // ---- closing barrier + flag reset (replay determinism) ----
  __syncthreads();
  if (tid == 0) {
    unsigned my = *((volatile unsigned*)&g_bgen[grp*32]);
    if (atomicAdd(&g_bcnt[grp*32], 1u) == 7u) {
      atomicExch(&g_bcnt[grp*32], 0u);
      atomicExch(&g_bgen[grp*32], my + 1u);
    }
    while (*((volatile unsigned*)&g_bgen[grp*32]) == my) { }
    __stcg(&g_flag[bA][htile], 0u);
    __stcg(&g_flag[bB][htile], 0u);
  }
}

extern "C" void kernel_launch(void* const* d_in, const int* in_sizes, int n_in,
                              void* d_out, int out_size) {
  const float* x     = (const float*)d_in[0];
  const float* W_in  = (const float*)d_in[1];
  const float* b_in  = (const float*)d_in[2];
  const float* W_rec = (const float*)d_in[3];
  const float* W_out = (const float*)d_in[4];
  const float* b_out = (const float*)d_in[5];
  float* out = (float*)d_out;

  cudaFuncSetAttribute(bnn_kernel,
                       cudaFuncAttributeMaxDynamicSharedMemorySize, SMEM_BYTES);
  bnn_kernel<<<NBLK, NTHR, SMEM_BYTES>>>(x, W_in, b_in, W_rec, W_out, b_out, out);
}

// round 17
// speedup vs baseline: 1.1321x; 1.1321x over previous
#include <cuda_runtime.h>
#include <cuda_bf16.h>
#include <cstdint>

#define T_STEPS 1000
#define BATCH   256
#define NIN     128
#define NHID    512
#define NOUT    128

#define NBLK 128
#define NTHR 384
#define BT 16      // batch rows per CTA
#define HT 64      // hidden cols per CTA

// smem: double-buffered bf16 s tiles (hi, lo), row stride 520 bf16 = 1040 B
#define SBUF0   0
#define SBUF1   33280                  // buf stride: 2*16*1040 (hi at +0, lo at +16640)
#define SLO_OFF 16640
#define XT_B    66560                  // 2 buffers x 16 rows x 272 B = 8704
#define WIN_B   75264                  // W_in fragments: 8w x 8ks x 32lane x 8B = 16384
#define OLO_B   91648                  // readout-lo exchange [16][18] f32 = 1152
#define SMEM_BYTES (OLO_B + 16*18*4)   // 92800 B

// bf16 hi/lo s rings (2 slots), b-major, u32 = 2 bf16
__device__ unsigned g_rh[2][BATCH][NHID/2];
__device__ unsigned g_rl[2][BATCH][NHID/2];
// flag barrier state: flags[btile][htile] (128B line per btile)
__device__ unsigned g_flag[16][32];
// closing atomic barrier (generation style; replay-monotonic)
__device__ unsigned g_bcnt[16*32];
__device__ unsigned g_bgen[16*32];

typedef unsigned long long u64;

__device__ __forceinline__ uint32_t smem_u32(const void* p) {
  uint32_t a;
  asm("{ .reg .u64 t; cvta.to.shared.u64 t, %1; cvt.u32.u64 %0, t; }"
      : "=r"(a) : "l"(p));
  return a;
}
__device__ __forceinline__ uint32_t pk2(float lo, float hi) {
  unsigned short a = __bfloat16_as_ushort(__float2bfloat16_rn(lo));
  unsigned short b = __bfloat16_as_ushort(__float2bfloat16_rn(hi));
  return (uint32_t)a | ((uint32_t)b << 16);
}
#define LDSM4(r0,r1,r2,r3,addr) \
  asm volatile("ldmatrix.sync.aligned.m8n8.x4.shared.b16 {%0,%1,%2,%3}, [%4];" \
    : "=r"(r0),"=r"(r1),"=r"(r2),"=r"(r3) : "r"(addr))
#define MMA16816(d, a0,a1,a2,a3, b0,b1) \
  asm volatile("mma.sync.aligned.m16n8k16.row.col.f32.bf16.bf16.f32 " \
    "{%0,%1,%2,%3}, {%4,%5,%6,%7}, {%8,%9}, {%0,%1,%2,%3};" \
    : "+f"((d)[0]),"+f"((d)[1]),"+f"((d)[2]),"+f"((d)[3]) \
    : "r"(a0),"r"(a1),"r"(a2),"r"(a3), "r"(b0),"r"(b1))

// acquire-correct flag poll: volatile L2 loads; fence before returning
__device__ __forceinline__ void poll_flags(const unsigned* fbase, unsigned want) {
  for (;;) {
    unsigned f0, f1, f2, f3, f4, f5, f6, f7;
    asm volatile("ld.global.cg.v4.u32 {%0,%1,%2,%3}, [%4];"
                 : "=r"(f0), "=r"(f1), "=r"(f2), "=r"(f3) : "l"(fbase));
    asm volatile("ld.global.cg.v4.u32 {%0,%1,%2,%3}, [%4];"
                 : "=r"(f4), "=r"(f5), "=r"(f6), "=r"(f7) : "l"(fbase + 4));
    if (f0 >= want && f1 >= want && f2 >= want && f3 >= want &&
        f4 >= want && f5 >= want && f6 >= want && f7 >= want) break;
  }
  asm volatile("fence.acq_rel.gpu;" ::: "memory");   // acquire
}

__global__ void __launch_bounds__(NTHR, 1)
bnn_kernel(const float* __restrict__ x,     // [T, B, NIN]
           const float* __restrict__ W_in,  // [NHID, NIN]
           const float* __restrict__ b_in,  // [NHID]
           const float* __restrict__ W_rec, // [NHID, NHID]
           const float* __restrict__ W_out, // [NOUT, NHID]
           const float* __restrict__ b_out, // [NOUT]
           float* __restrict__ out)         // [T, B, NOUT]
{
  extern __shared__ char smc[];
  const uint32_t smb = smem_u32(smc);
  float* olo = (float*)(smc + OLO_B);   // [16][18]

  const int tid = threadIdx.x;
  const int blk = blockIdx.x;
  const int btile = blk >> 3;           // 16 independent b-tiles
  const int htile = blk & 7;            // 8 h-tiles = barrier group members
  const int b0 = btile * BT;
  const int h0 = htile * HT;
  const int o0 = htile * 16;
  const int w  = tid >> 5;              // 0..11
  const int lane = tid & 31;

  // ---- B fragments (W_rec / W_out hi / W_out lo) in registers ----
  uint32_t bf0[32], bf1[32];
  {
    const int nn = w*8 + (lane >> 2);
    const float* wr;
    bool is_lo = false;
    if (nn < 64) wr = W_rec + (size_t)(h0 + nn)*NHID;
    else if (nn < 80) wr = W_out + (size_t)(o0 + nn - 64)*NHID;
    else { wr = W_out + (size_t)(o0 + nn - 80)*NHID; is_lo = true; }
    #pragma unroll
    for (int ks = 0; ks < 32; ++ks) {
      int k0 = ks*16 + (lane & 3)*2;
      float w00 = __ldg(wr + k0),     w01 = __ldg(wr + k0 + 1);
      float w10 = __ldg(wr + k0 + 8), w11 = __ldg(wr + k0 + 9);
      if (is_lo) {
        w00 -= __bfloat162float(__float2bfloat16_rn(w00));
        w01 -= __bfloat162float(__float2bfloat16_rn(w01));
        w10 -= __bfloat162float(__float2bfloat16_rn(w10));
        w11 -= __bfloat162float(__float2bfloat16_rn(w11));
      }
      bf0[ks] = pk2(w00, w01);
      bf1[ks] = pk2(w10, w11);
    }
  }

  // ---- W_in B-fragments into smem (update warps own their slice) ----
  if (w < 8) {
    const float* wr = W_in + (size_t)(h0 + w*8 + (lane >> 2))*NIN;
    #pragma unroll
    for (int ks = 0; ks < 8; ++ks) {
      int k0 = ks*16 + (lane & 3)*2;
      uint32_t lo = pk2(__ldg(wr + k0),     __ldg(wr + k0 + 1));
      uint32_t hi = pk2(__ldg(wr + k0 + 8), __ldg(wr + k0 + 9));
      *(uint2*)(smc + WIN_B + (size_t)((w*8 + ks)*32 + lane)*8) = make_uint2(lo, hi);
    }
  }

  // ---- zero s buffer 0 (s[-1] = 0); stage x[0] -> XT[0] ----
  for (int i = tid; i < 8320; i += NTHR) ((uint32_t*)(smc + SBUF0))[i] = 0u;
  {
    const float4* xr = (const float4*)x + (size_t)b0*32;
    for (int i = tid; i < 512; i += NTHR) {
      int row = i >> 5, c4 = i & 31;
      float4 vv = __ldcg(xr + row*32 + c4);
      *(uint2*)(smc + XT_B + row*272 + c4*8) = make_uint2(pk2(vv.x, vv.y), pk2(vv.z, vv.w));
    }
  }
  __syncthreads();

  // per-lane ldmatrix offset within an s buffer
  const uint32_t aOff = (uint32_t)(lane & 15)*1040 + (uint32_t)((lane >> 4) & 1)*16;
  const uint32_t aX0 = smb + XT_B + (uint32_t)(lane & 15)*272
                     + (uint32_t)((lane >> 4) & 1)*16;
  const char* winp = smc + WIN_B + (size_t)(w*8*32 + lane)*8;

  const int r  = lane >> 2;
  const int hh = h0 + w*8 + (lane & 3)*2;

  if (w < 8) {
    // ================= UPDATE PIPELINE (warps 0-7, tids 0-255) =============
    float2 bin = *(const float2*)(b_in + hh);
    float v[4]  = {0.f,0.f,0.f,0.f};
    float a0s[4] = {0.f,0.f,0.f,0.f};
    float a1s[4] = {0.f,0.f,0.f,0.f};
    float sp[4] = {0.f,0.f,0.f,0.f};

    asm volatile("membar.cta;" ::: "memory");
    asm volatile("bar.arrive 5, 384;" ::: "memory");   // prime: buf0 hi ready

    for (int t = 0; t < T_STEPS; ++t) {
      asm volatile("bar.sync 4, 384;" ::: "memory");   // x[t] staged; readout done with buf[(t+1)&1]
      const uint32_t aH = smb + ((t & 1) ? SBUF1 : SBUF0) + aOff;
      const uint32_t aX = aX0 + (uint32_t)(t & 1)*4352;

      float dA[4]={0,0,0,0}, dB[4]={0,0,0,0};
      float dC[4]={0,0,0,0}, dD[4]={0,0,0,0}, dX[4]={0,0,0,0};
      #pragma unroll
      for (int ks = 0; ks < 32; ks += 4) {
        uint32_t f0,f1,f2,f3; LDSM4(f0,f1,f2,f3, aH + (uint32_t)ks*32);
        MMA16816(dA, f0,f1,f2,f3, bf0[ks], bf1[ks]);
        uint32_t g0,g1,g2,g3; LDSM4(g0,g1,g2,g3, aH + (uint32_t)(ks+1)*32);
        MMA16816(dB, g0,g1,g2,g3, bf0[ks+1], bf1[ks+1]);
        uint32_t p0,p1,p2,p3; LDSM4(p0,p1,p2,p3, aH + (uint32_t)(ks+2)*32);
        MMA16816(dC, p0,p1,p2,p3, bf0[ks+2], bf1[ks+2]);
        uint32_t q0,q1,q2,q3; LDSM4(q0,q1,q2,q3, aH + (uint32_t)(ks+3)*32);
        MMA16816(dD, q0,q1,q2,q3, bf0[ks+3], bf1[ks+3]);
      }
      #pragma unroll
      for (int ks = 0; ks < 8; ++ks) {
        uint2 wf = *(const uint2*)(winp + ks*256);
        uint32_t f0,f1,f2,f3; LDSM4(f0,f1,f2,f3, aX + (uint32_t)ks*32);
        MMA16816(dX, f0,f1,f2,f3, wf.x, wf.y);
      }

      // ---- GLIFR update ----
      float bv[4] = {bin.x, bin.y, bin.x, bin.y};
      #pragma unroll
      for (int j = 0; j < 4; ++j) {
        float y  = 0.5f*(dA[j] + dB[j] + dC[j] + dD[j] + dX[j] + bv[j]);
        a0s[j] = fmaf(a0s[j],  0.85f, -0.05f*sp[j]);
        a1s[j] = fmaf(a1s[j], -0.5f,  -0.05f*sp[j]);
        float it = y + a0s[j] + a1s[j] + 700.0f;
        v[j]  = v[j]*0.99f*(1.0f - 0.05f*sp[j]) + 0.00101953125f*it;
        sp[j] = 20.0f / (1.0f + __expf(-v[j]*0.02f));
      }
      // publish bf16 hi/lo
      const int slot = t & 1;
      float h0f = __bfloat162float(__float2bfloat16_rn(sp[0]));
      float h1f = __bfloat162float(__float2bfloat16_rn(sp[1]));
      float h2f = __bfloat162float(__float2bfloat16_rn(sp[2]));
      float h3f = __bfloat162float(__float2bfloat16_rn(sp[3]));
      __stcg(&g_rh[slot][b0 + r][hh >> 1],     pk2(sp[0], sp[1]));
      __stcg(&g_rh[slot][b0 + r + 8][hh >> 1], pk2(sp[2], sp[3]));
      __stcg(&g_rl[slot][b0 + r][hh >> 1],     pk2(sp[0] - h0f, sp[1] - h1f));
      __stcg(&g_rl[slot][b0 + r + 8][hh >> 1], pk2(sp[2] - h2f, sp[3] - h3f));

      asm volatile("bar.sync 1, 256;" ::: "memory");
      if (tid == 0) {
        asm volatile("fence.acq_rel.gpu;" ::: "memory");   // release
        __stcg(&g_flag[btile][htile], (unsigned)(t + 1));
      }
      poll_flags(&g_flag[btile][0], (unsigned)(t + 1));

      // ---- restage hi: rings slot t&1 -> buf[(t+1)&1] hi ----
      {
        char* db = smc + (((t + 1) & 1) ? SBUF1 : SBUF0);
        int row = tid >> 4, c0 = (tid & 15)*4;
        const uint4* src = (const uint4*)&g_rh[slot][b0 + row][0];
        #pragma unroll
        for (int j = 0; j < 4; ++j) {
          uint4 vv = __ldcg(src + c0 + j);
          *(uint4*)(db + row*1040 + (c0 + j)*16) = vv;
        }
      }
      asm volatile("bar.sync 1, 256;" ::: "memory");       // restage visible to update warps
      asm volatile("membar.cta;" ::: "memory");
      asm volatile("bar.arrive 5, 384;" ::: "memory");     // hi buf[(t+1)&1] ready for readout
    }
  } else {
    // ================= READOUT PIPELINE (warps 8-11, tids 256-383) =========
    const int oc = ((w - 8) & 1)*8 + (lane & 3)*2;
    float2 bo2 = make_float2(0.f, 0.f);
    if (w < 10) bo2 = make_float2(__ldg(b_out + o0 + oc),
                                  __ldg(b_out + o0 + oc + 1));

    asm volatile("membar.cta;" ::: "memory");
    asm volatile("bar.arrive 4, 384;" ::: "memory");   // prime: x[0] staged

    for (int t = 0; t <= T_STEPS; ++t) {
      asm volatile("bar.sync 5, 384;" ::: "memory");   // hi buf[t&1] ready (s[t-1])
      const uint32_t aH = smb + ((t & 1) ? SBUF1 : SBUF0) + aOff;
      const uint32_t aL = aH + SLO_OFF;
      float d0, d1, d2, d3;

      if (w < 10) {
        // readout hi GEMM: W_out_hi @ (s_hi + s_lo), 4 chains
        float dh0[4]={0,0,0,0}, dh1[4]={0,0,0,0};
        float dl0[4]={0,0,0,0}, dl1[4]={0,0,0,0};
        #pragma unroll
        for (int ks = 0; ks < 32; ks += 2) {
          uint32_t f0,f1,f2,f3; LDSM4(f0,f1,f2,f3, aH + (uint32_t)ks*32);
          MMA16816(dh0, f0,f1,f2,f3, bf0[ks], bf1[ks]);
          uint32_t g0,g1,g2,g3; LDSM4(g0,g1,g2,g3, aH + (uint32_t)(ks+1)*32);
          MMA16816(dh1, g0,g1,g2,g3, bf0[ks+1], bf1[ks+1]);
          uint32_t p0,p1,p2,p3; LDSM4(p0,p1,p2,p3, aL + (uint32_t)ks*32);
          MMA16816(dl0, p0,p1,p2,p3, bf0[ks], bf1[ks]);
          uint32_t q0,q1,q2,q3; LDSM4(q0,q1,q2,q3, aL + (uint32_t)(ks+1)*32);
          MMA16816(dl1, q0,q1,q2,q3, bf0[ks+1], bf1[ks+1]);
        }
        d0 = dh0[0]+dh1[0]+dl0[0]+dl1[0];
        d1 = dh0[1]+dh1[1]+dl0[1]+dl1[1];
        d2 = dh0[2]+dh1[2]+dl0[2]+dl1[2];
        d3 = dh0[3]+dh1[3]+dl0[3]+dl1[3];
      } else {
        // readout lo GEMM: W_out_lo @ s_hi, 4 chains
        float dA[4]={0,0,0,0}, dB[4]={0,0,0,0};
        float dC[4]={0,0,0,0}, dD[4]={0,0,0,0};
        #pragma unroll
        for (int ks = 0; ks < 32; ks += 4) {
          uint32_t f0,f1,f2,f3; LDSM4(f0,f1,f2,f3, aH + (uint32_t)ks*32);
          MMA16816(dA, f0,f1,f2,f3, bf0[ks], bf1[ks]);
          uint32_t g0,g1,g2,g3; LDSM4(g0,g1,g2,g3, aH + (uint32_t)(ks+1)*32);
          MMA16816(dB, g0,g1,g2,g3, bf0[ks+1], bf1[ks+1]);
          uint32_t p0,p1,p2,p3; LDSM4(p0,p1,p2,p3, aH + (uint32_t)(ks+2)*32);
          MMA16816(dC, p0,p1,p2,p3, bf0[ks+2], bf1[ks+2]);
          uint32_t q0,q1,q2,q3; LDSM4(q0,q1,q2,q3, aH + (uint32_t)(ks+3)*32);
          MMA16816(dD, q0,q1,q2,q3, bf0[ks+3], bf1[ks+3]);
        }
        int c = (w - 10)*8 + (lane & 3)*2;
        olo[r*18 + c]           = dA[0]+dB[0]+dC[0]+dD[0];
        olo[r*18 + c + 1]       = dA[1]+dB[1]+dC[1]+dD[1];
        olo[(r+8)*18 + c]       = dA[2]+dB[2]+dC[2]+dD[2];
        olo[(r+8)*18 + c + 1]   = dA[3]+dB[3]+dC[3]+dD[3];
        d0 = d1 = d2 = d3 = 0.f;
      }
      asm volatile("bar.sync 8, 128;" ::: "memory");
      if (w < 10 && t >= 1) {
        float* op = out + (size_t)(t - 1)*BATCH*NOUT + (size_t)(b0 + r)*NOUT + o0 + oc;
        *(float2*)op = make_float2(d0 + olo[r*18 + oc] + bo2.x,
                                   d1 + olo[r*18 + oc + 1] + bo2.y);
        float* op2 = op + 8*NOUT;
        *(float2*)op2 = make_float2(d2 + olo[(r + 8)*18 + oc] + bo2.x,
                                    d3 + olo[(r + 8)*18 + oc + 1] + bo2.y);
      }
      asm volatile("bar.sync 8, 128;" ::: "memory");   // olo reads done before next write

      if (t < T_STEPS) {
        // ---- stage x[t+1] -> XT[(t+1)&1] (FIXED indexing) ----
        int tn = (t + 1 < T_STEPS) ? t + 1 : (T_STEPS - 1);
        const float4* xr = (const float4*)(x + (size_t)tn*BATCH*NIN) + (size_t)b0*32;
        char* dst = smc + XT_B + ((t + 1) & 1)*4352;
        int i = (w - 8)*32 + lane;       // 128 threads x 4 rounds cover 512
        #pragma unroll
        for (int jj = 0; jj < 4; ++jj, i += 128) {
          int row = i >> 5, c4 = i & 31;
          float4 vv = __ldcg(xr + row*32 + c4);
          *(uint2*)(dst + row*272 + c4*8) = make_uint2(pk2(vv.x, vv.y), pk2(vv.z, vv.w));
        }

        poll_flags(&g_flag[btile][0], (unsigned)(t + 1));

        // ---- restage lo: rings slot t&1 -> buf[(t+1)&1] lo ----
        {
          const int slot = t & 1;
          char* db = smc + (((t + 1) & 1) ? SBUF1 : SBUF0) + SLO_OFF;
          int rt = tid - 256;            // 0..127
          int row = rt >> 3, c0 = (rt & 7)*8;
          const uint4* src = (const uint4*)&g_rl[slot][b0 + row][0];
          #pragma unroll
          for (int j = 0; j < 8; ++j) {
            uint4 vv = __ldcg(src + c0 + j);
            *(uint4*)(db + row*1040 + (c0 + j)*16) = vv;
          }
        }
        asm volatile("membar.cta;" ::: "memory");
        asm volatile("bar.arrive 4, 384;" ::: "memory");   // x staged + reads done
      }
    }
  }

  // ---- closing barrier + flag reset (replay determinism) ----
  __syncthreads();
  if (tid == 0) {
    unsigned my = *((volatile unsigned*)&g_bgen[btile*32]);
    if (atomicAdd(&g_bcnt[btile*32], 1u) == 7u) {
      atomicExch(&g_bcnt[btile*32], 0u);
      atomicExch(&g_bgen[btile*32], my + 1u);
    }
    while (*((volatile unsigned*)&g_bgen[btile*32]) == my) { }
    __stcg(&g_flag[btile][htile], 0u);
  }
}

extern "C" void kernel_launch(void* const* d_in, const int* in_sizes, int n_in,
                              void* d_out, int out_size) {
  const float* x     = (const float*)d_in[0];
  const float* W_in  = (const float*)d_in[1];
  const float* b_in  = (const float*)d_in[2];
  const float* W_rec = (const float*)d_in[3];
  const float* W_out = (const float*)d_in[4];
  const float* b_out = (const float*)d_in[5];
  float* out = (float*)d_out;

  cudaFuncSetAttribute(bnn_kernel,
                       cudaFuncAttributeMaxDynamicSharedMemorySize, SMEM_BYTES);
  bnn_kernel<<<NBLK, NTHR, SMEM_BYTES>>>(x, W_in, b_in, W_rec, W_out, b_out, out);
}